// round 10
// baseline (speedup 1.0000x reference)
#include <cuda_runtime.h>
#include <cstdint>

// ---------------------------------------------------------------------------
// Problem constants
// ---------------------------------------------------------------------------
#define M_ELEMS   2560000      // N_NODES * N_FEAT
#define M_VEC4    640000       // M_ELEMS / 4
#define K_DROP    256000       // num drop (10%)
#define N_EDGES   640000
#define CAP_EQ    65536

typedef unsigned long long ull;

// ---------------------------------------------------------------------------
// Device scratch (globals: no allocation allowed)
// ---------------------------------------------------------------------------
__device__ __align__(16) float g_poss[M_ELEMS];
__device__ unsigned g_hist1[4096];
__device__ unsigned g_hist2[4096];
__device__ unsigned g_hist3[256];
__device__ unsigned g_below;
__device__ unsigned g_sel1;
__device__ unsigned g_sel12;
__device__ unsigned g_thresh;
__device__ int      g_ties;
__device__ unsigned g_eq_cnt;
__device__ int      g_eq_cut;
__device__ int      g_eq_idx[CAP_EQ];
__device__ unsigned g_done1, g_done2, g_done3, g_done4;

// ---------------------------------------------------------------------------
// f32x2 helpers (Blackwell packed fp32 pipe)
// ---------------------------------------------------------------------------
__device__ __forceinline__ ull pk2(float lo, float hi) {
    ull r; asm("mov.b64 %0, {%1, %2};" : "=l"(r) : "f"(lo), "f"(hi)); return r;
}
__device__ __forceinline__ void upk2(ull v, float& lo, float& hi) {
    asm("mov.b64 {%0, %1}, %2;" : "=f"(lo), "=f"(hi) : "l"(v));
}
__device__ __forceinline__ void fma2(ull& d, ull a, ull b) {
    asm("fma.rn.f32x2 %0, %1, %2, %0;" : "+l"(d) : "l"(a), "l"(b));
}

// ---------------------------------------------------------------------------
// Accurate fp32 exp/log (immune to --use_fast_math substitution)
// ---------------------------------------------------------------------------
__device__ __forceinline__ float expf_acc(float x) {
    float n = rintf(x * 1.4426950408889634f);
    float r = fmaf(-n, 0.693359375f, x);          // ln2_hi
    r = fmaf(n, 2.1219444045e-4f, r);             // ln2_hi - ln2
    float p = 1.9841269841e-4f;
    p = fmaf(p, r, 1.3888888889e-3f);
    p = fmaf(p, r, 8.3333333333e-3f);
    p = fmaf(p, r, 4.1666666667e-2f);
    p = fmaf(p, r, 1.6666666667e-1f);
    p = fmaf(p, r, 0.5f);
    p = fmaf(p, r, 1.0f);
    p = fmaf(p, r, 1.0f);
    int ni = (int)n;
    float sc = __int_as_float((ni + 127) << 23);
    return p * sc;
}

__device__ __forceinline__ float logf_acc(float x) {
    int ix = __float_as_int(x);
    int e = ((ix >> 23) & 0xFF) - 127;
    float m = __int_as_float((ix & 0x007FFFFF) | 0x3F800000);  // [1,2)
    if (m > 1.41421356f) { m *= 0.5f; e += 1; }
    float fe = (float)e;
    float t = __fdiv_rn(m - 1.0f, m + 1.0f);
    float t2 = t * t;
    float q = 0.2222222222f;
    q = fmaf(q, t2, 0.2857142857f);
    q = fmaf(q, t2, 0.4f);
    q = fmaf(q, t2, 0.6666666667f);
    q = fmaf(q, t2, 2.0f);
    float lm = t * q;                              // log(m) via atanh series
    return fmaf(fe, 0.693359375f, fmaf(-fe, 2.1219444045e-4f, lm));
}

// ---------------------------------------------------------------------------
// Scalar epilogue on the final logit pair z: log-softmax + gumbel + softmax
// ---------------------------------------------------------------------------
__device__ __forceinline__ float finish_z(ull z, float u0, float u1) {
    float z0, z1; upk2(z, z0, z1);
    float zm = fmaxf(z0, z1);
    float e0 = expf_acc(z0 - zm), e1 = expf_acc(z1 - zm);
    float s = e0 + e1;
    float p0 = __fdiv_rn(e0, s), p1 = __fdiv_rn(e1, s);
    float l0 = logf_acc(p0 + 1e-8f), l1 = logf_acc(p1 + 1e-8f);
    float g0 = -logf_acc(-logf_acc(u0));
    float g1 = -logf_acc(-logf_acc(u1));
    float a0 = l0 + g0, a1 = l1 + g1;
    float am = fmaxf(a0, a1);
    float f0 = expf_acc(a0 - am), f1 = expf_acc(a1 - am);
    float y0 = __fdiv_rn(f0, f0 + f1);
    float poss = 1.0f - y0;
    return fminf(fmaxf(poss, 1e-6f), 1.0f);
}

// ---------------------------------------------------------------------------
// Selection scan stage (runs in the last-finishing block of a hist kernel).
// Finds the bin where the running count crosses K_DROP. (Proven in R6.)
// ---------------------------------------------------------------------------
template<int NT>
__device__ __forceinline__ void scan_sel(volatile unsigned* hist, int nbins,
                                         int stage, unsigned* sh) {
    int per = nbins / NT;
    int t = threadIdx.x;
    unsigned local = 0;
    for (int i = 0; i < per; i++) local += hist[t * per + i];
    sh[t] = local;
    __syncthreads();
    for (int off = 1; off < NT; off <<= 1) {
        unsigned add = (t >= off) ? sh[t - off] : 0u;
        __syncthreads();
        sh[t] += add;
        __syncthreads();
    }
    unsigned incl = sh[t], excl = incl - local;
    unsigned prior = g_below;
    if (prior + excl < K_DROP && prior + incl >= K_DROP) {
        unsigned run = prior + excl;
        int bin = -1;
        for (int i = 0; i < per; i++) {
            unsigned c = hist[t * per + i];
            if (run + c >= K_DROP) { bin = t * per + i; break; }
            run += c;
        }
        if (stage == 0)      { g_sel1 = (unsigned)bin;                   g_below = run; }
        else if (stage == 1) { g_sel12 = (g_sel1 << 12) | (unsigned)bin; g_below = run; }
        else { g_thresh = (g_sel12 << 8) | (unsigned)bin; g_below = run;
               g_ties = (int)(K_DROP - run); }
    }
}

// ---------------------------------------------------------------------------
// K1: fused MLP -> poss.  JP=8 accumulator chunks (4 chunks of 8 jp-pairs)
// with immediate ReLU+W2 fold into z after each chunk.  Lower register
// pressure -> 5 CTAs/SM.  Arithmetic order identical to R9 (k ascending per
// j, j ascending in the fold) -> bit-identical poss.
// ---------------------------------------------------------------------------
__global__ __launch_bounds__(128, 5) void poss_kernel(
    const float* __restrict__ eig, const float* __restrict__ uni,
    const float* __restrict__ W1, const float* __restrict__ b1,
    const float* __restrict__ W2, const float* __restrict__ b2)
{
    __shared__ __align__(16) ull sW1[1024];   // [k=0..31][jp=0..31]
    __shared__ __align__(16) ull sW2[64];     // per j: (W2[j][0], W2[j][1])
    __shared__ __align__(16) ull sB1[32];     // b1 pairs
    __shared__ float sb2[2];

    int tid = threadIdx.x;
    const ull* W1u = (const ull*)W1;
    const ull* W2u = (const ull*)W2;
    const ull* b1u = (const ull*)b1;
    for (int i = tid; i < 1024; i += 128) sW1[i] = W1u[i];
    if (tid < 64) sW2[tid] = W2u[tid];
    if (tid < 32) sB1[tid] = b1u[tid];
    if (tid < 2)  sb2[tid] = b2[tid];
    __syncthreads();

    int e0 = blockIdx.x * 256 + tid;
    int e1 = e0 + 128;

    const float4* A0 = (const float4*)(eig + (size_t)e0 * 32);
    const float4* A1 = (const float4*)(eig + (size_t)e1 * 32);

    ull z0 = pk2(sb2[0], sb2[1]);
    ull z1 = z0;

#pragma unroll 1
    for (int jc = 0; jc < 4; jc++) {          // jp in [jc*8, jc*8+8)
        ull acc0[8], acc1[8];
#pragma unroll
        for (int p = 0; p < 8; p++) {
            ull b = sB1[jc * 8 + p];
            acc0[p] = b; acc1[p] = b;
        }

#pragma unroll
        for (int kc = 0; kc < 4; kc++) {
            float4 x0a = A0[kc * 2], x0b = A0[kc * 2 + 1];
            float4 x1a = A1[kc * 2], x1b = A1[kc * 2 + 1];
            float a0v[8] = {x0a.x, x0a.y, x0a.z, x0a.w, x0b.x, x0b.y, x0b.z, x0b.w};
            float a1v[8] = {x1a.x, x1a.y, x1a.z, x1a.w, x1b.x, x1b.y, x1b.z, x1b.w};
#pragma unroll
            for (int kk = 0; kk < 8; kk++) {
                ull aa0 = pk2(a0v[kk], a0v[kk]);
                ull aa1 = pk2(a1v[kk], a1v[kk]);
                const ulonglong2* wrow =
                    (const ulonglong2*)&sW1[(kc * 8 + kk) * 32 + jc * 8];
#pragma unroll
                for (int p2 = 0; p2 < 4; p2++) {   // 2 jp per LDS.128
                    ulonglong2 w = wrow[p2];
                    fma2(acc0[2 * p2],     aa0, w.x);
                    fma2(acc1[2 * p2],     aa1, w.x);
                    fma2(acc0[2 * p2 + 1], aa0, w.y);
                    fma2(acc1[2 * p2 + 1], aa1, w.y);
                }
            }
        }

        // fold: ReLU + layer-2 into z (same op order as previous epilogue)
#pragma unroll
        for (int p = 0; p < 8; p++) {
            int jp = jc * 8 + p;
            ull w2a = sW2[2 * jp], w2b = sW2[2 * jp + 1];
            float h0, h1; upk2(acc0[p], h0, h1);
            h0 = fmaxf(h0, 0.0f); h1 = fmaxf(h1, 0.0f);
            fma2(z0, pk2(h0, h0), w2a);
            fma2(z0, pk2(h1, h1), w2b);
            float g0, g1; upk2(acc1[p], g0, g1);
            g0 = fmaxf(g0, 0.0f); g1 = fmaxf(g1, 0.0f);
            fma2(z1, pk2(g0, g0), w2a);
            fma2(z1, pk2(g1, g1), w2b);
        }
    }

    const float2* U = (const float2*)uni;
    float2 uu0 = U[e0];
    float2 uu1 = U[e1];
    g_poss[e0] = finish_z(z0, uu0.x, uu0.y);
    g_poss[e1] = finish_z(z1, uu1.x, uu1.y);
}

// ---------------------------------------------------------------------------
// Zeroing
// ---------------------------------------------------------------------------
__global__ void zero_kernel() {   // <<<16,256>>>
    int i = blockIdx.x * blockDim.x + threadIdx.x;
    g_hist1[i] = 0;
    g_hist2[i] = 0;
    if (i < 256) g_hist3[i] = 0;
    if (i == 0) {
        g_below = 0; g_eq_cnt = 0; g_ties = 0; g_eq_cut = -1;
        g_done1 = 0; g_done2 = 0; g_done3 = 0; g_done4 = 0;
    }
}

// ---------------------------------------------------------------------------
// Tail pass-through (int64 inputs live on device as int32)
// ---------------------------------------------------------------------------
__global__ void tail_ei_kernel(const int* __restrict__ ei, float* __restrict__ out,
                               int count) {
    int i = blockIdx.x * blockDim.x + threadIdx.x;
    if (i < count) out[M_ELEMS + i] = (float)ei[i];
}
__global__ void tail_ew_kernel(const float* __restrict__ ew, float* __restrict__ out,
                               int count) {
    int i = blockIdx.x * blockDim.x + threadIdx.x;
    if (i < count) out[M_ELEMS + 2 * N_EDGES + i] = ew[i];
}

// ---------------------------------------------------------------------------
// Radix select passes (vectorized uint4; poss > 0 so uint order == float
// order).  Scans fused into the last-finishing block (pattern proven in R6).
// ---------------------------------------------------------------------------
__global__ __launch_bounds__(256) void hist1_kernel() {   // <<<2500,256>>>
    __shared__ unsigned sh[4096];
    __shared__ bool s_last;
    for (int i = threadIdx.x; i < 4096; i += 256) sh[i] = 0;
    __syncthreads();
    int i = blockIdx.x * blockDim.x + threadIdx.x;
    uint4 v = ((const uint4*)g_poss)[i];
    atomicAdd(&sh[v.x >> 20], 1u);
    atomicAdd(&sh[v.y >> 20], 1u);
    atomicAdd(&sh[v.z >> 20], 1u);
    atomicAdd(&sh[v.w >> 20], 1u);
    __syncthreads();
    for (int j = threadIdx.x; j < 4096; j += 256) {
        unsigned c = sh[j];
        if (c) atomicAdd(&g_hist1[j], c);
    }
    __threadfence();
    __syncthreads();
    if (threadIdx.x == 0) s_last = (atomicAdd(&g_done1, 1u) == gridDim.x - 1);
    __syncthreads();
    if (s_last) scan_sel<256>(g_hist1, 4096, 0, sh);
}

__global__ __launch_bounds__(256) void hist2_kernel() {   // <<<2500,256>>>
    __shared__ unsigned sh[256];
    __shared__ bool s_last;
    unsigned sel = g_sel1;
    int i = blockIdx.x * blockDim.x + threadIdx.x;
    uint4 v = ((const uint4*)g_poss)[i];
    if ((v.x >> 20) == sel) atomicAdd(&g_hist2[(v.x >> 8) & 0xFFF], 1u);
    if ((v.y >> 20) == sel) atomicAdd(&g_hist2[(v.y >> 8) & 0xFFF], 1u);
    if ((v.z >> 20) == sel) atomicAdd(&g_hist2[(v.z >> 8) & 0xFFF], 1u);
    if ((v.w >> 20) == sel) atomicAdd(&g_hist2[(v.w >> 8) & 0xFFF], 1u);
    __threadfence();
    __syncthreads();
    if (threadIdx.x == 0) s_last = (atomicAdd(&g_done2, 1u) == gridDim.x - 1);
    __syncthreads();
    if (s_last) scan_sel<256>(g_hist2, 4096, 1, sh);
}

__global__ __launch_bounds__(256) void hist3_kernel() {   // <<<2500,256>>>
    __shared__ unsigned sh[256];
    __shared__ bool s_last;
    unsigned sel = g_sel12;
    int i = blockIdx.x * blockDim.x + threadIdx.x;
    uint4 v = ((const uint4*)g_poss)[i];
    if ((v.x >> 8) == sel) atomicAdd(&g_hist3[v.x & 0xFF], 1u);
    if ((v.y >> 8) == sel) atomicAdd(&g_hist3[v.y & 0xFF], 1u);
    if ((v.z >> 8) == sel) atomicAdd(&g_hist3[v.z & 0xFF], 1u);
    if ((v.w >> 8) == sel) atomicAdd(&g_hist3[v.w & 0xFF], 1u);
    __threadfence();
    __syncthreads();
    if (threadIdx.x == 0) s_last = (atomicAdd(&g_done3, 1u) == gridDim.x - 1);
    __syncthreads();
    if (s_last) scan_sel<256>(g_hist3, 256, 2, sh);
}

// eq collect + tie-break (last block). Ties resolved lowest-index-first.
__global__ __launch_bounds__(256) void eq_kernel() {   // <<<2500,256>>>
    __shared__ bool s_last;
    unsigned T = g_thresh;
    int i = blockIdx.x * blockDim.x + threadIdx.x;
    uint4 v = ((const uint4*)g_poss)[i];
    int b = 4 * i;
    if (v.x == T) { unsigned p = atomicAdd(&g_eq_cnt, 1u); if (p < CAP_EQ) g_eq_idx[p] = b; }
    if (v.y == T) { unsigned p = atomicAdd(&g_eq_cnt, 1u); if (p < CAP_EQ) g_eq_idx[p] = b + 1; }
    if (v.z == T) { unsigned p = atomicAdd(&g_eq_cnt, 1u); if (p < CAP_EQ) g_eq_idx[p] = b + 2; }
    if (v.w == T) { unsigned p = atomicAdd(&g_eq_cnt, 1u); if (p < CAP_EQ) g_eq_idx[p] = b + 3; }
    __threadfence();
    __syncthreads();
    if (threadIdx.x == 0) s_last = (atomicAdd(&g_done4, 1u) == gridDim.x - 1);
    __syncthreads();
    if (s_last) {
        int cnt = (int)min(g_eq_cnt, (unsigned)CAP_EQ);
        int ties = g_ties;
        if (ties > 0) {
            volatile int* eqi = g_eq_idx;
            for (int e = threadIdx.x; e < cnt; e += blockDim.x) {
                int my = eqi[e];
                int r = 0;
                for (int o = 0; o < cnt; o++) r += (eqi[o] < my);
                if (r == ties - 1) g_eq_cut = my;   // ties-th smallest index
            }
        }
    }
}

// ---------------------------------------------------------------------------
// Finalize (vectorized): x_new[i] = x[i] * poss[i] if selected else x[i]
// ---------------------------------------------------------------------------
__global__ __launch_bounds__(256) void finalize4_kernel(const float* __restrict__ x,
                                                        float* __restrict__ out) {
    int i = blockIdx.x * blockDim.x + threadIdx.x;   // < M_VEC4
    uint4 pv = ((const uint4*)g_poss)[i];
    float4 xv = ((const float4*)x)[i];
    unsigned T = g_thresh;
    int cut = g_eq_cut;
    int b = 4 * i;
    float4 o;
    o.x = xv.x * (((pv.x < T) || (pv.x == T && b     <= cut)) ? __uint_as_float(pv.x) : 1.0f);
    o.y = xv.y * (((pv.y < T) || (pv.y == T && b + 1 <= cut)) ? __uint_as_float(pv.y) : 1.0f);
    o.z = xv.z * (((pv.z < T) || (pv.z == T && b + 2 <= cut)) ? __uint_as_float(pv.z) : 1.0f);
    o.w = xv.w * (((pv.w < T) || (pv.w == T && b + 3 <= cut)) ? __uint_as_float(pv.w) : 1.0f);
    ((float4*)out)[i] = o;
}

__global__ void finalize_scalar_kernel(const float* __restrict__ x,
                                       float* __restrict__ out, int n) {
    int i = blockIdx.x * blockDim.x + threadIdx.x;
    if (i >= n) return;
    float p = g_poss[i];
    unsigned k = __float_as_uint(p);
    unsigned T = g_thresh;
    bool sel = (k < T) || (k == T && i <= g_eq_cut);
    out[i] = x[i] * (sel ? p : 1.0f);
}

// ---------------------------------------------------------------------------
// Launch.  poss_kernel at MY index 3: harness prepends 2 launches, so
// ncu's  -s 5 -c 1  captures it.
// ---------------------------------------------------------------------------
extern "C" void kernel_launch(void* const* d_in, const int* in_sizes, int n_in,
                              void* d_out, int out_size) {
    const float* x   = (const float*)d_in[0];
    const int*   ei  = (const int*)d_in[1];      // int64 -> int32 on device
    const float* ew  = (const float*)d_in[2];
    const float* eig = (const float*)d_in[3];
    const float* uni = (const float*)d_in[4];
    const float* W1  = (const float*)d_in[5];
    const float* b1  = (const float*)d_in[6];
    const float* W2  = (const float*)d_in[7];
    const float* b2  = (const float*)d_in[8];
    float* out = (float*)d_out;
    (void)in_sizes; (void)n_in;

    int rem = out_size - M_ELEMS;
    int nei = rem > 0 ? (rem < 2 * N_EDGES ? rem : 2 * N_EDGES) : 0;
    int nw  = rem - nei; if (nw < 0) nw = 0; if (nw > N_EDGES) nw = N_EDGES;

    zero_kernel<<<16, 256>>>();                                   // idx 0
    tail_ei_kernel<<<5000, 256>>>(ei, out, nei);                  // idx 1
    tail_ew_kernel<<<2500, 256>>>(ew, out, nw);                   // idx 2
    poss_kernel<<<10000, 128>>>(eig, uni, W1, b1, W2, b2);        // idx 3 (profiled)
    hist1_kernel<<<2500, 256>>>();                                // idx 4
    hist2_kernel<<<2500, 256>>>();                                // idx 5
    hist3_kernel<<<2500, 256>>>();                                // idx 6
    eq_kernel<<<2500, 256>>>();                                   // idx 7
    if (out_size >= M_ELEMS) {
        finalize4_kernel<<<2500, 256>>>(x, out);                  // idx 8
    } else {
        finalize_scalar_kernel<<<(out_size + 255) / 256, 256>>>(x, out, out_size);
    }
}

// round 12
// speedup vs baseline: 1.2609x; 1.2609x over previous
#include <cuda_runtime.h>
#include <cstdint>

// ---------------------------------------------------------------------------
// Problem constants
// ---------------------------------------------------------------------------
#define M_ELEMS   2560000      // N_NODES * N_FEAT
#define M_VEC4    640000       // M_ELEMS / 4
#define K_DROP    256000       // num drop (10%)
#define N_EDGES   640000
#define CAP_EQ    65536

typedef unsigned long long ull;

// ---------------------------------------------------------------------------
// Device scratch (globals: no allocation allowed)
// ---------------------------------------------------------------------------
__device__ __align__(16) float g_poss[M_ELEMS];
__device__ unsigned g_hist1[4096];
__device__ unsigned g_hist2[4096];
__device__ unsigned g_hist3[256];
__device__ unsigned g_below;
__device__ unsigned g_sel1;
__device__ unsigned g_sel12;
__device__ unsigned g_thresh;
__device__ int      g_ties;
__device__ unsigned g_eq_cnt;
__device__ int      g_eq_cut;
__device__ int      g_eq_idx[CAP_EQ];

// ---------------------------------------------------------------------------
// f32x2 helpers (Blackwell packed fp32 pipe)
// ---------------------------------------------------------------------------
__device__ __forceinline__ ull pk2(float lo, float hi) {
    ull r; asm("mov.b64 %0, {%1, %2};" : "=l"(r) : "f"(lo), "f"(hi)); return r;
}
__device__ __forceinline__ void upk2(ull v, float& lo, float& hi) {
    asm("mov.b64 {%0, %1}, %2;" : "=f"(lo), "=f"(hi) : "l"(v));
}
__device__ __forceinline__ void fma2(ull& d, ull a, ull b) {
    asm("fma.rn.f32x2 %0, %1, %2, %0;" : "+l"(d) : "l"(a), "l"(b));
}

// ---------------------------------------------------------------------------
// Accurate fp32 exp/log (immune to --use_fast_math substitution)
// ---------------------------------------------------------------------------
__device__ __forceinline__ float expf_acc(float x) {
    float n = rintf(x * 1.4426950408889634f);
    float r = fmaf(-n, 0.693359375f, x);          // ln2_hi
    r = fmaf(n, 2.1219444045e-4f, r);             // ln2_hi - ln2
    float p = 1.9841269841e-4f;
    p = fmaf(p, r, 1.3888888889e-3f);
    p = fmaf(p, r, 8.3333333333e-3f);
    p = fmaf(p, r, 4.1666666667e-2f);
    p = fmaf(p, r, 1.6666666667e-1f);
    p = fmaf(p, r, 0.5f);
    p = fmaf(p, r, 1.0f);
    p = fmaf(p, r, 1.0f);
    int ni = (int)n;
    float sc = __int_as_float((ni + 127) << 23);
    return p * sc;
}

__device__ __forceinline__ float logf_acc(float x) {
    int ix = __float_as_int(x);
    int e = ((ix >> 23) & 0xFF) - 127;
    float m = __int_as_float((ix & 0x007FFFFF) | 0x3F800000);  // [1,2)
    if (m > 1.41421356f) { m *= 0.5f; e += 1; }
    float fe = (float)e;
    float t = __fdiv_rn(m - 1.0f, m + 1.0f);
    float t2 = t * t;
    float q = 0.2222222222f;
    q = fmaf(q, t2, 0.2857142857f);
    q = fmaf(q, t2, 0.4f);
    q = fmaf(q, t2, 0.6666666667f);
    q = fmaf(q, t2, 2.0f);
    float lm = t * q;                              // log(m) via atanh series
    return fmaf(fe, 0.693359375f, fmaf(-fe, 2.1219444045e-4f, lm));
}

// ---------------------------------------------------------------------------
// Scalar epilogue on the final logit pair z: log-softmax + gumbel + softmax
// ---------------------------------------------------------------------------
__device__ __forceinline__ float finish_z(ull z, float u0, float u1) {
    float z0, z1; upk2(z, z0, z1);
    float zm = fmaxf(z0, z1);
    float e0 = expf_acc(z0 - zm), e1 = expf_acc(z1 - zm);
    float s = e0 + e1;
    float p0 = __fdiv_rn(e0, s), p1 = __fdiv_rn(e1, s);
    float l0 = logf_acc(p0 + 1e-8f), l1 = logf_acc(p1 + 1e-8f);
    float g0 = -logf_acc(-logf_acc(u0));
    float g1 = -logf_acc(-logf_acc(u1));
    float a0 = l0 + g0, a1 = l1 + g1;
    float am = fmaxf(a0, a1);
    float f0 = expf_acc(a0 - am), f1 = expf_acc(a1 - am);
    float y0 = __fdiv_rn(f0, f0 + f1);
    float poss = 1.0f - y0;
    return fminf(fmaxf(poss, 1e-6f), 1.0f);
}

// ---------------------------------------------------------------------------
// K1: fused MLP -> poss.  R9 structure (JP=16 chunks, 2 elems/thread) with
// coalesced shared-memory staging of the 256x32 eigen tile (padded to 36
// floats/row).  Replaces per-thread strided LDG (32 lines/instr) with
// coalesced LDG (4 lines/instr) + conflict-floor LDS.  Arithmetic order
// identical to R9 -> bit-identical poss.
// ---------------------------------------------------------------------------
#define ROW_PAD 36   // 32 floats + 4 pad: kills stride-128B bank pathology

__global__ __launch_bounds__(128, 4) void poss_kernel(
    const float* __restrict__ eig, const float* __restrict__ uni,
    const float* __restrict__ W1, const float* __restrict__ b1,
    const float* __restrict__ W2, const float* __restrict__ b2)
{
    __shared__ __align__(16) ull sW1[1024];     // [k=0..31][jp=0..31]  8 KB
    __shared__ __align__(16) ull sW2[64];       // per j: (W2[j][0], W2[j][1])
    __shared__ __align__(16) ull sB1[32];       // b1 pairs
    __shared__ float sb2[2];
    __shared__ __align__(16) float sA[256 * ROW_PAD];   // 36 KB eigen tile

    int tid = threadIdx.x;
    const ull* W1u = (const ull*)W1;
    const ull* W2u = (const ull*)W2;
    const ull* b1u = (const ull*)b1;
    for (int i = tid; i < 1024; i += 128) sW1[i] = W1u[i];
    if (tid < 64) sW2[tid] = W2u[tid];
    if (tid < 32) sB1[tid] = b1u[tid];
    if (tid < 2)  sb2[tid] = b2[tid];

    // Coalesced staging: 256 rows x 32 floats = 2048 float4, 16 per thread.
    {
        const float4* E4 = (const float4*)(eig + (size_t)blockIdx.x * 256 * 32);
#pragma unroll
        for (int it = 0; it < 16; it++) {
            int idx4 = tid + it * 128;          // consecutive -> coalesced
            int row = idx4 >> 3, c4 = idx4 & 7;
            float4 v = E4[idx4];
            *(float4*)&sA[row * ROW_PAD + c4 * 4] = v;
        }
    }
    __syncthreads();

    int e0 = blockIdx.x * 256 + tid;
    int e1 = e0 + 128;
    const float* a0p = &sA[tid * ROW_PAD];
    const float* a1p = &sA[(tid + 128) * ROW_PAD];

    ull z0 = pk2(sb2[0], sb2[1]);
    ull z1 = z0;

#pragma unroll 1
    for (int jc = 0; jc < 2; jc++) {          // jp in [jc*16, jc*16+16)
        ull acc0[16], acc1[16];
#pragma unroll
        for (int p = 0; p < 16; p++) {
            ull b = sB1[jc * 16 + p];
            acc0[p] = b; acc1[p] = b;
        }

#pragma unroll
        for (int kc = 0; kc < 4; kc++) {
            float4 x0a = *(const float4*)&a0p[kc * 8];
            float4 x0b = *(const float4*)&a0p[kc * 8 + 4];
            float4 x1a = *(const float4*)&a1p[kc * 8];
            float4 x1b = *(const float4*)&a1p[kc * 8 + 4];
            float a0v[8] = {x0a.x, x0a.y, x0a.z, x0a.w, x0b.x, x0b.y, x0b.z, x0b.w};
            float a1v[8] = {x1a.x, x1a.y, x1a.z, x1a.w, x1b.x, x1b.y, x1b.z, x1b.w};
#pragma unroll
            for (int kk = 0; kk < 8; kk++) {
                ull aa0 = pk2(a0v[kk], a0v[kk]);
                ull aa1 = pk2(a1v[kk], a1v[kk]);
                const ulonglong2* wrow =
                    (const ulonglong2*)&sW1[(kc * 8 + kk) * 32 + jc * 16];
#pragma unroll
                for (int p2 = 0; p2 < 8; p2++) {   // 2 jp per LDS.128
                    ulonglong2 w = wrow[p2];
                    fma2(acc0[2 * p2],     aa0, w.x);
                    fma2(acc1[2 * p2],     aa1, w.x);
                    fma2(acc0[2 * p2 + 1], aa0, w.y);
                    fma2(acc1[2 * p2 + 1], aa1, w.y);
                }
            }
        }

        // fold: ReLU + layer-2 into z (same op order as R9)
#pragma unroll
        for (int p = 0; p < 16; p++) {
            int jp = jc * 16 + p;
            ull w2a = sW2[2 * jp], w2b = sW2[2 * jp + 1];
            float h0, h1; upk2(acc0[p], h0, h1);
            h0 = fmaxf(h0, 0.0f); h1 = fmaxf(h1, 0.0f);
            fma2(z0, pk2(h0, h0), w2a);
            fma2(z0, pk2(h1, h1), w2b);
            float g0, g1; upk2(acc1[p], g0, g1);
            g0 = fmaxf(g0, 0.0f); g1 = fmaxf(g1, 0.0f);
            fma2(z1, pk2(g0, g0), w2a);
            fma2(z1, pk2(g1, g1), w2b);
        }
    }

    const float2* U = (const float2*)uni;
    float2 uu0 = U[e0];
    float2 uu1 = U[e1];
    g_poss[e0] = finish_z(z0, uu0.x, uu0.y);
    g_poss[e1] = finish_z(z1, uu1.x, uu1.y);
}

// ---------------------------------------------------------------------------
// Zeroing
// ---------------------------------------------------------------------------
__global__ void zero_kernel() {   // <<<16,256>>>
    int i = blockIdx.x * blockDim.x + threadIdx.x;
    g_hist1[i] = 0;
    g_hist2[i] = 0;
    if (i < 256) g_hist3[i] = 0;
    if (i == 0) { g_below = 0; g_eq_cnt = 0; g_ties = 0; g_eq_cut = -1; }
}

// ---------------------------------------------------------------------------
// Tail pass-through (int64 inputs live on device as int32)
// ---------------------------------------------------------------------------
__global__ void tail_ei_kernel(const int* __restrict__ ei, float* __restrict__ out,
                               int count) {
    int i = blockIdx.x * blockDim.x + threadIdx.x;
    if (i < count) out[M_ELEMS + i] = (float)ei[i];
}
__global__ void tail_ew_kernel(const float* __restrict__ ew, float* __restrict__ out,
                               int count) {
    int i = blockIdx.x * blockDim.x + threadIdx.x;
    if (i < count) out[M_ELEMS + 2 * N_EDGES + i] = ew[i];
}

// ---------------------------------------------------------------------------
// Radix select passes (vectorized uint4; poss > 0 so uint order == float order)
// ---------------------------------------------------------------------------
__global__ __launch_bounds__(256) void hist1_kernel() {   // <<<2500,256>>>
    __shared__ unsigned sh[4096];
    for (int i = threadIdx.x; i < 4096; i += 256) sh[i] = 0;
    __syncthreads();
    int i = blockIdx.x * blockDim.x + threadIdx.x;
    uint4 v = ((const uint4*)g_poss)[i];
    atomicAdd(&sh[v.x >> 20], 1u);
    atomicAdd(&sh[v.y >> 20], 1u);
    atomicAdd(&sh[v.z >> 20], 1u);
    atomicAdd(&sh[v.w >> 20], 1u);
    __syncthreads();
    for (int j = threadIdx.x; j < 4096; j += 256) {
        unsigned c = sh[j];
        if (c) atomicAdd(&g_hist1[j], c);
    }
}

__global__ __launch_bounds__(256) void hist2_kernel() {   // <<<2500,256>>>
    unsigned sel = g_sel1;
    int i = blockIdx.x * blockDim.x + threadIdx.x;
    uint4 v = ((const uint4*)g_poss)[i];
    if ((v.x >> 20) == sel) atomicAdd(&g_hist2[(v.x >> 8) & 0xFFF], 1u);
    if ((v.y >> 20) == sel) atomicAdd(&g_hist2[(v.y >> 8) & 0xFFF], 1u);
    if ((v.z >> 20) == sel) atomicAdd(&g_hist2[(v.z >> 8) & 0xFFF], 1u);
    if ((v.w >> 20) == sel) atomicAdd(&g_hist2[(v.w >> 8) & 0xFFF], 1u);
}

__global__ __launch_bounds__(256) void hist3_kernel() {   // <<<2500,256>>>
    unsigned sel = g_sel12;
    int i = blockIdx.x * blockDim.x + threadIdx.x;
    uint4 v = ((const uint4*)g_poss)[i];
    if ((v.x >> 8) == sel) atomicAdd(&g_hist3[v.x & 0xFF], 1u);
    if ((v.y >> 8) == sel) atomicAdd(&g_hist3[v.y & 0xFF], 1u);
    if ((v.z >> 8) == sel) atomicAdd(&g_hist3[v.z & 0xFF], 1u);
    if ((v.w >> 8) == sel) atomicAdd(&g_hist3[v.w & 0xFF], 1u);
}

__global__ void scan_kernel(int stage) {
    __shared__ unsigned sh[256];
    const unsigned* hist = (stage == 0) ? g_hist1 : (stage == 1) ? g_hist2 : g_hist3;
    int nbins = (stage == 2) ? 256 : 4096;
    int per = nbins / 256;
    unsigned t = threadIdx.x;

    unsigned local = 0;
    for (int i = 0; i < per; i++) local += hist[t * per + i];
    sh[t] = local;
    __syncthreads();
    for (int off = 1; off < 256; off <<= 1) {
        unsigned add = (t >= (unsigned)off) ? sh[t - off] : 0u;
        __syncthreads();
        sh[t] += add;
        __syncthreads();
    }
    unsigned incl = sh[t];
    unsigned excl = incl - local;
    unsigned prior = g_below;
    const unsigned target = K_DROP;

    if (prior + excl < target && prior + incl >= target) {
        unsigned run = prior + excl;
        int bin = -1;
        for (int i = 0; i < per; i++) {
            unsigned c = hist[t * per + i];
            if (run + c >= target) { bin = t * per + i; break; }
            run += c;
        }
        if (stage == 0)      { g_sel1 = (unsigned)bin;                   g_below = run; }
        else if (stage == 1) { g_sel12 = (g_sel1 << 12) | (unsigned)bin; g_below = run; }
        else {
            g_thresh = (g_sel12 << 8) | (unsigned)bin;
            g_below = run;
            g_ties = (int)(target - run);
        }
    }
}

__global__ __launch_bounds__(256) void eq_collect_kernel() {   // <<<2500,256>>>
    unsigned T = g_thresh;
    int i = blockIdx.x * blockDim.x + threadIdx.x;
    uint4 v = ((const uint4*)g_poss)[i];
    int b = 4 * i;
    if (v.x == T) { unsigned p = atomicAdd(&g_eq_cnt, 1u); if (p < CAP_EQ) g_eq_idx[p] = b; }
    if (v.y == T) { unsigned p = atomicAdd(&g_eq_cnt, 1u); if (p < CAP_EQ) g_eq_idx[p] = b + 1; }
    if (v.z == T) { unsigned p = atomicAdd(&g_eq_cnt, 1u); if (p < CAP_EQ) g_eq_idx[p] = b + 2; }
    if (v.w == T) { unsigned p = atomicAdd(&g_eq_cnt, 1u); if (p < CAP_EQ) g_eq_idx[p] = b + 3; }
}

__global__ void eqcut_kernel() {
    int cnt = (int)min(g_eq_cnt, (unsigned)CAP_EQ);
    int ties = g_ties;
    if (threadIdx.x == 0 && ties <= 0) g_eq_cut = -1;
    if (ties > 0) {
        for (int e = threadIdx.x; e < cnt; e += blockDim.x) {
            int my = g_eq_idx[e];
            int r = 0;
            for (int o = 0; o < cnt; o++) r += (g_eq_idx[o] < my);
            if (r == ties - 1) g_eq_cut = my;   // ties-th smallest index
        }
    }
}

// ---------------------------------------------------------------------------
// Finalize (vectorized): x_new[i] = x[i] * poss[i] if selected else x[i]
// ---------------------------------------------------------------------------
__global__ __launch_bounds__(256) void finalize4_kernel(const float* __restrict__ x,
                                                        float* __restrict__ out) {
    int i = blockIdx.x * blockDim.x + threadIdx.x;   // < M_VEC4
    uint4 pv = ((const uint4*)g_poss)[i];
    float4 xv = ((const float4*)x)[i];
    unsigned T = g_thresh;
    int cut = g_eq_cut;
    int b = 4 * i;
    float4 o;
    o.x = xv.x * (((pv.x < T) || (pv.x == T && b     <= cut)) ? __uint_as_float(pv.x) : 1.0f);
    o.y = xv.y * (((pv.y < T) || (pv.y == T && b + 1 <= cut)) ? __uint_as_float(pv.y) : 1.0f);
    o.z = xv.z * (((pv.z < T) || (pv.z == T && b + 2 <= cut)) ? __uint_as_float(pv.z) : 1.0f);
    o.w = xv.w * (((pv.w < T) || (pv.w == T && b + 3 <= cut)) ? __uint_as_float(pv.w) : 1.0f);
    ((float4*)out)[i] = o;
}

__global__ void finalize_scalar_kernel(const float* __restrict__ x,
                                       float* __restrict__ out, int n) {
    int i = blockIdx.x * blockDim.x + threadIdx.x;
    if (i >= n) return;
    float p = g_poss[i];
    unsigned k = __float_as_uint(p);
    unsigned T = g_thresh;
    bool sel = (k < T) || (k == T && i <= g_eq_cut);
    out[i] = x[i] * (sel ? p : 1.0f);
}

// ---------------------------------------------------------------------------
// Launch.  poss_kernel at MY index 3: harness prepends 2 launches, so
// ncu's  -s 5 -c 1  captures it.  Separate scan kernels (R9 structure —
// fusion measured slower in R10).
// ---------------------------------------------------------------------------
extern "C" void kernel_launch(void* const* d_in, const int* in_sizes, int n_in,
                              void* d_out, int out_size) {
    const float* x   = (const float*)d_in[0];
    const int*   ei  = (const int*)d_in[1];      // int64 -> int32 on device
    const float* ew  = (const float*)d_in[2];
    const float* eig = (const float*)d_in[3];
    const float* uni = (const float*)d_in[4];
    const float* W1  = (const float*)d_in[5];
    const float* b1  = (const float*)d_in[6];
    const float* W2  = (const float*)d_in[7];
    const float* b2  = (const float*)d_in[8];
    float* out = (float*)d_out;
    (void)in_sizes; (void)n_in;

    int rem = out_size - M_ELEMS;
    int nei = rem > 0 ? (rem < 2 * N_EDGES ? rem : 2 * N_EDGES) : 0;
    int nw  = rem - nei; if (nw < 0) nw = 0; if (nw > N_EDGES) nw = N_EDGES;

    zero_kernel<<<16, 256>>>();                                   // idx 0
    tail_ei_kernel<<<5000, 256>>>(ei, out, nei);                  // idx 1
    tail_ew_kernel<<<2500, 256>>>(ew, out, nw);                   // idx 2
    poss_kernel<<<10000, 128>>>(eig, uni, W1, b1, W2, b2);        // idx 3 (profiled)
    hist1_kernel<<<2500, 256>>>();                                // idx 4
    scan_kernel<<<1, 256>>>(0);                                   // idx 5
    hist2_kernel<<<2500, 256>>>();                                // idx 6
    scan_kernel<<<1, 256>>>(1);                                   // idx 7
    hist3_kernel<<<2500, 256>>>();                                // idx 8
    scan_kernel<<<1, 256>>>(2);                                   // idx 9
    eq_collect_kernel<<<2500, 256>>>();                           // idx 10
    eqcut_kernel<<<1, 256>>>();                                   // idx 11
    if (out_size >= M_ELEMS) {
        finalize4_kernel<<<2500, 256>>>(x, out);                  // idx 12
    } else {
        finalize_scalar_kernel<<<(out_size + 255) / 256, 256>>>(x, out, out_size);
    }
}